// round 3
// baseline (speedup 1.0000x reference)
#include <cuda_runtime.h>
#include <math.h>

#define E_NUM  131072
#define NN     32768
#define DM     256
#define DE     128
#define TD     64
#define HIDN   512
#define MSGD   256
#define INDIM  704

// ---------------- scratch (static device globals; no allocation) ----------
__device__ float g_h   [(size_t)E_NUM * HIDN];   // 268 MB
__device__ float g_msg [(size_t)E_NUM * MSGD];   // 134 MB
__device__ float g_sums[(size_t)NN * MSGD];      // 33.5 MB (indexed by id)
__device__ float g_agg [(size_t)NN * MSGD];      // 33.5 MB (indexed by unique slot)
__device__ float g_gih [(size_t)NN * 3 * DM];    // 100 MB
__device__ float g_ghh [(size_t)NN * 3 * DM];    // 100 MB
__device__ int   g_cnt [NN];
__device__ int   g_uid [NN];
__device__ int   g_is64;

// ---------------- dtype detector for dst_ids (int32 vs int64) -------------
__global__ void k_detect(const int* ids32) {
    if (threadIdx.x == 0 && blockIdx.x == 0) {
        int z = 0;
        // if the buffer is int64, every odd 32-bit word (high half) is 0
        for (int i = 1; i < 64; i += 2) z |= ids32[i];
        g_is64 = (z == 0) ? 1 : 0;
    }
}

__device__ __forceinline__ int load_id(const void* idsv, int e) {
    if (g_is64) return (int)((const long long*)idsv)[e];
    return ((const int*)idsv)[e];
}

// ---------------- zero / init (must run every launch: graph replays) ------
__global__ void k_zero(float* out, int write_ids) {
    int idx = blockIdx.x * blockDim.x + threadIdx.x;  // NN*MSGD threads
    g_sums[idx] = 0.0f;
    if (idx < NN) {
        g_cnt[idx] = 0;
        g_uid[idx] = NN;
        if (write_ids) out[idx] = (float)NN;   // fill value for padded slots
    }
}

// ---------------- per-id counts -------------------------------------------
__global__ void k_count(const void* idsv) {
    int e = blockIdx.x * blockDim.x + threadIdx.x;
    if (e < E_NUM) {
        int id = load_id(idsv, e);
        atomicAdd(&g_cnt[id], 1);
    }
}

// ---------------- single-block scan: sorted unique ids + ranks ------------
__global__ void k_scan(float* out, int write_ids) {
    __shared__ int s[1024];
    int tid = threadIdx.x;
    int base = tid * 32;
    int loc = 0;
    for (int i = 0; i < 32; i++) loc += (g_cnt[base + i] > 0) ? 1 : 0;
    s[tid] = loc;
    __syncthreads();
    for (int off = 1; off < 1024; off <<= 1) {
        int v = (tid >= off) ? s[tid - off] : 0;
        __syncthreads();
        s[tid] += v;
        __syncthreads();
    }
    int r = s[tid] - loc;   // exclusive prefix
    for (int i = 0; i < 32; i++) {
        int id = base + i;
        if (g_cnt[id] > 0) {
            g_uid[r] = id;
            if (write_ids) out[r] = (float)id;
            r++;
        }
    }
}

// ---------------- scatter msg into per-id sums ----------------------------
__global__ void k_scatter(const void* idsv) {
    int idx = blockIdx.x * blockDim.x + threadIdx.x;  // E*64
    int e  = idx >> 6;
    int c4 = (idx & 63) << 2;
    int id = load_id(idsv, e);
    float4 m = *reinterpret_cast<const float4*>(g_msg + (size_t)e * MSGD + c4);
    float* d = g_sums + (size_t)id * MSGD + c4;
    atomicAdd(d + 0, m.x);
    atomicAdd(d + 1, m.y);
    atomicAdd(d + 2, m.z);
    atomicAdd(d + 3, m.w);
}

// ---------------- agg = sums/count gathered into unique-slot order --------
__global__ void k_agg() {
    int idx = blockIdx.x * blockDim.x + threadIdx.x;  // NN*64
    int u  = idx >> 6;
    int c4 = (idx & 63) << 2;
    int id = g_uid[u];
    float4 o = make_float4(0.f, 0.f, 0.f, 0.f);
    if (id < NN) {
        float cnt = (float)g_cnt[id];       // >= 1 here, matches max(counts,1)
        float4 s = *reinterpret_cast<const float4*>(g_sums + (size_t)id * MSGD + c4);
        o.x = s.x / cnt; o.y = s.y / cnt; o.z = s.z / cnt; o.w = s.w / cnt;
    }
    *reinterpret_cast<float4*>(g_agg + (size_t)u * MSGD + c4) = o;
}

// ---------------- generic TN SGEMM: C = A(MxK) * B(NxK)^T + bias ----------
// All dims divisible by tile sizes (M%128==0, N%128==0, K%16==0).
#define BM 128
#define BN 128
#define BKK 16

template <int CONCAT>
__global__ void __launch_bounds__(256)
gemm_tn(const float* __restrict__ A, const float* __restrict__ B,
        const float* __restrict__ bias, float* __restrict__ C,
        int M, int N, int K, int relu,
        const float* __restrict__ srcm, const float* __restrict__ dstm,
        const float* __restrict__ edgef, const float* __restrict__ rt,
        const float* __restrict__ tw, const float* __restrict__ tb)
{
    __shared__ float As[BKK][BM];
    __shared__ float Bs[BKK][BN];

    const int tid = threadIdx.x;
    const int tx = tid & 15;
    const int ty = tid >> 4;
    const int rowBase = blockIdx.y * BM;
    const int colBase = blockIdx.x * BN;

    float acc[8][8];
#pragma unroll
    for (int i = 0; i < 8; i++)
#pragma unroll
        for (int j = 0; j < 8; j++) acc[i][j] = 0.0f;

    for (int k0 = 0; k0 < K; k0 += BKK) {
        // ---- load A tile (128 rows x 16 k), transposed into As[k][m]
#pragma unroll
        for (int l = 0; l < 2; l++) {
            int c   = l * 256 + tid;
            int row = c >> 2;
            int kc  = (c & 3) << 2;
            int gk  = k0 + kc;
            int gr  = rowBase + row;
            float4 v;
            if (CONCAT) {
                if (gk < 256) {
                    v = *reinterpret_cast<const float4*>(srcm + (size_t)gr * 256 + gk);
                } else if (gk < 512) {
                    v = *reinterpret_cast<const float4*>(dstm + (size_t)gr * 256 + (gk - 256));
                } else if (gk < 640) {
                    v = *reinterpret_cast<const float4*>(edgef + (size_t)gr * 128 + (gk - 512));
                } else {
                    float r = rt[gr];
                    int j = gk - 640;
                    v.x = cosf(fmaf(r, tw[j + 0], tb[j + 0]));
                    v.y = cosf(fmaf(r, tw[j + 1], tb[j + 1]));
                    v.z = cosf(fmaf(r, tw[j + 2], tb[j + 2]));
                    v.w = cosf(fmaf(r, tw[j + 3], tb[j + 3]));
                }
            } else {
                v = *reinterpret_cast<const float4*>(A + (size_t)gr * K + gk);
            }
            As[kc + 0][row] = v.x;
            As[kc + 1][row] = v.y;
            As[kc + 2][row] = v.z;
            As[kc + 3][row] = v.w;
        }
        // ---- load B tile (128 n x 16 k), transposed into Bs[k][n]
#pragma unroll
        for (int l = 0; l < 2; l++) {
            int c  = l * 256 + tid;
            int n  = c >> 2;
            int kc = (c & 3) << 2;
            float4 v = *reinterpret_cast<const float4*>(B + (size_t)(colBase + n) * K + k0 + kc);
            Bs[kc + 0][n] = v.x;
            Bs[kc + 1][n] = v.y;
            Bs[kc + 2][n] = v.z;
            Bs[kc + 3][n] = v.w;
        }
        __syncthreads();

#pragma unroll
        for (int k = 0; k < BKK; k++) {
            float a[8], b[8];
            float4 a0 = *reinterpret_cast<const float4*>(&As[k][ty * 8]);
            float4 a1 = *reinterpret_cast<const float4*>(&As[k][ty * 8 + 4]);
            float4 b0 = *reinterpret_cast<const float4*>(&Bs[k][tx * 8]);
            float4 b1 = *reinterpret_cast<const float4*>(&Bs[k][tx * 8 + 4]);
            a[0] = a0.x; a[1] = a0.y; a[2] = a0.z; a[3] = a0.w;
            a[4] = a1.x; a[5] = a1.y; a[6] = a1.z; a[7] = a1.w;
            b[0] = b0.x; b[1] = b0.y; b[2] = b0.z; b[3] = b0.w;
            b[4] = b1.x; b[5] = b1.y; b[6] = b1.z; b[7] = b1.w;
#pragma unroll
            for (int i = 0; i < 8; i++)
#pragma unroll
                for (int j = 0; j < 8; j++)
                    acc[i][j] = fmaf(a[i], b[j], acc[i][j]);
        }
        __syncthreads();
    }

    // ---- epilogue: bias (+ optional relu), float4 stores
    float bcol[8];
#pragma unroll
    for (int j = 0; j < 8; j++) bcol[j] = bias[colBase + tx * 8 + j];

#pragma unroll
    for (int i = 0; i < 8; i++) {
        int r = rowBase + ty * 8 + i;
#pragma unroll
        for (int j = 0; j < 8; j += 4) {
            float4 o;
            o.x = acc[i][j + 0] + bcol[j + 0];
            o.y = acc[i][j + 1] + bcol[j + 1];
            o.z = acc[i][j + 2] + bcol[j + 2];
            o.w = acc[i][j + 3] + bcol[j + 3];
            if (relu) {
                o.x = fmaxf(o.x, 0.f);
                o.y = fmaxf(o.y, 0.f);
                o.z = fmaxf(o.z, 0.f);
                o.w = fmaxf(o.w, 0.f);
            }
            *reinterpret_cast<float4*>(C + (size_t)r * N + colBase + tx * 8 + j) = o;
        }
    }
}

// ---------------- GRU gates + output --------------------------------------
__global__ void k_gate(const float* __restrict__ dstm, float* __restrict__ out,
                       int mem_off) {
    int idx = blockIdx.x * blockDim.x + threadIdx.x;  // NN*DM
    int u = idx >> 8;
    int c = idx & 255;
    const float* gi = g_gih + (size_t)u * (3 * DM);
    const float* gh = g_ghh + (size_t)u * (3 * DM);
    float r = 1.0f / (1.0f + expf(-(gi[c] + gh[c])));
    float z = 1.0f / (1.0f + expf(-(gi[256 + c] + gh[256 + c])));
    float n = tanhf(gi[512 + c] + r * gh[512 + c]);
    float prev = dstm[idx];            // dst_memories[:NN], positional
    out[mem_off + idx] = (1.0f - z) * n + z * prev;
}

// ---------------- launch ---------------------------------------------------
extern "C" void kernel_launch(void* const* d_in, const int* in_sizes, int n_in,
                              void* d_out, int out_size)
{
    const float* rel_time = (const float*)d_in[0];
    const float* srcm     = (const float*)d_in[1];
    const float* dstm     = (const float*)d_in[2];
    const float* edgef    = (const float*)d_in[3];
    const void*  idsv     =               d_in[4];
    const float* tw       = (const float*)d_in[5];
    const float* tb       = (const float*)d_in[6];
    const float* w1       = (const float*)d_in[7];
    const float* b1       = (const float*)d_in[8];
    const float* w2       = (const float*)d_in[9];
    const float* b2       = (const float*)d_in[10];
    const float* wih      = (const float*)d_in[11];
    const float* whh      = (const float*)d_in[12];
    const float* bih      = (const float*)d_in[13];
    const float* bhh      = (const float*)d_in[14];
    float* out = (float*)d_out;

    // Output layout: [unique_ids as float (NN)] ++ [memories (NN*DM)].
    // Guard: if the harness only holds memories, skip the ids region.
    int write_ids = (out_size >= NN + NN * DM) ? 1 : 0;
    int mem_off   = write_ids ? NN : 0;

    float *p_h, *p_msg, *p_agg, *p_gih, *p_ghh;
    cudaGetSymbolAddress((void**)&p_h,   g_h);
    cudaGetSymbolAddress((void**)&p_msg, g_msg);
    cudaGetSymbolAddress((void**)&p_agg, g_agg);
    cudaGetSymbolAddress((void**)&p_gih, g_gih);
    cudaGetSymbolAddress((void**)&p_ghh, g_ghh);

    // 1) detect ids dtype; 2) zero per-launch state
    k_detect<<<1, 32>>>((const int*)idsv);
    k_zero<<<(NN * MSGD) / 256, 256>>>(out, write_ids);

    // 3) counts, 4) sorted-unique scan
    k_count<<<E_NUM / 256, 256>>>(idsv);
    k_scan<<<1, 1024>>>(out, write_ids);

    // 5) GEMM1: h = relu([src|dst|edge|t_enc] @ w1^T + b1)   (131072x704x512)
    gemm_tn<1><<<dim3(HIDN / BN, E_NUM / BM), 256>>>(
        nullptr, w1, b1, p_h, E_NUM, HIDN, INDIM, 1,
        srcm, dstm, edgef, rel_time, tw, tb);

    // 6) GEMM2: msg = h @ w2^T + b2                          (131072x512x256)
    gemm_tn<0><<<dim3(MSGD / BN, E_NUM / BM), 256>>>(
        p_h, w2, b2, p_msg, E_NUM, MSGD, HIDN, 0,
        nullptr, nullptr, nullptr, nullptr, nullptr, nullptr);

    // 7) scatter-add per-id sums, 8) build agg in slot order
    k_scatter<<<(E_NUM * 64) / 256, 256>>>(idsv);
    k_agg<<<(NN * 64) / 256, 256>>>();

    // 9) GRU GEMMs: gi = agg @ wih^T + bih ; gh = prev @ whh^T + bhh
    gemm_tn<0><<<dim3((3 * DM) / BN, NN / BM), 256>>>(
        p_agg, wih, bih, p_gih, NN, 3 * DM, MSGD, 0,
        nullptr, nullptr, nullptr, nullptr, nullptr, nullptr);
    gemm_tn<0><<<dim3((3 * DM) / BN, NN / BM), 256>>>(
        dstm, whh, bhh, p_ghh, NN, 3 * DM, DM, 0,
        nullptr, nullptr, nullptr, nullptr, nullptr, nullptr);

    // 10) gates + write memories
    k_gate<<<(NN * DM) / 256, 256>>>(dstm, out, mem_off);
}

// round 8
// speedup vs baseline: 3.0879x; 3.0879x over previous
#include <cuda_runtime.h>
#include <math.h>
#include <stdint.h>

#define E_NUM  131072
#define NN     32768
#define DM     256
#define HIDN   512
#define MSGD   256

// ---------------- scratch (static device globals; no allocation) ----------
__device__ float g_h   [(size_t)E_NUM * HIDN];    // 268 MB
__device__ float g_msg [(size_t)E_NUM * MSGD];    // 134 MB
__device__ float g_tenc[(size_t)E_NUM * 64];      // 33.5 MB
__device__ float g_sums[(size_t)NN * MSGD];       // 33.5 MB (indexed by id)
__device__ float g_agg [(size_t)NN * MSGD];       // 33.5 MB (unique-slot order)
__device__ float g_gih [(size_t)NN * 3 * DM];     // 100 MB
__device__ float g_ghh [(size_t)NN * 3 * DM];     // 100 MB
__device__ int   g_cnt [NN];
__device__ int   g_uid [NN];
__device__ int   g_is64;

// ---------------- helpers ---------------------------------------------------
__device__ __forceinline__ uint32_t smem_u32(const void* p) {
    uint32_t a;
    asm("{ .reg .u64 t; cvta.to.shared.u64 t, %1; cvt.u32.u64 %0, t; }"
        : "=r"(a) : "l"(p));
    return a;
}
__device__ __forceinline__ uint32_t lds_tf(const float* p) {
    uint32_t r;
    float f = *p;
    asm("cvt.rna.tf32.f32 %0, %1;" : "=r"(r) : "f"(f));
    return r;
}
__device__ __forceinline__ void cp16(uint32_t dst, const void* src) {
    asm volatile("cp.async.ca.shared.global [%0], [%1], 16;" :: "r"(dst), "l"(src));
}
template <int N>
__device__ __forceinline__ void cp_wait() {
    asm volatile("cp.async.wait_group %0;" :: "n"(N) : "memory");
}
__device__ __forceinline__ void mma8(float* d, const uint32_t* a, const uint32_t* b) {
    asm volatile("mma.sync.aligned.m16n8k8.row.col.f32.tf32.tf32.f32 "
                 "{%0,%1,%2,%3}, {%4,%5,%6,%7}, {%8,%9}, {%0,%1,%2,%3};"
                 : "+f"(d[0]), "+f"(d[1]), "+f"(d[2]), "+f"(d[3])
                 : "r"(a[0]), "r"(a[1]), "r"(a[2]), "r"(a[3]),
                   "r"(b[0]), "r"(b[1]));
}

// ---------------- dtype detector for dst_ids (int32 vs int64) -------------
__global__ void k_detect(const int* ids32) {
    if (threadIdx.x == 0 && blockIdx.x == 0) {
        int z = 0;
        for (int i = 1; i < 64; i += 2) z |= ids32[i];
        g_is64 = (z == 0) ? 1 : 0;
    }
}
__device__ __forceinline__ int load_id(const void* idsv, int e) {
    if (g_is64) return (int)((const long long*)idsv)[e];
    return ((const int*)idsv)[e];
}

// ---------------- per-launch init ------------------------------------------
__global__ void k_zero(float* out, int write_ids) {
    int idx = blockIdx.x * blockDim.x + threadIdx.x;  // NN*MSGD threads
    g_sums[idx] = 0.0f;
    if (idx < NN) {
        g_cnt[idx] = 0;
        g_uid[idx] = NN;
        if (write_ids) out[idx] = (float)NN;
    }
}

// ---------------- time encoding --------------------------------------------
__global__ void k_tenc(const float* __restrict__ rt, const float* __restrict__ tw,
                       const float* __restrict__ tb) {
    int idx = blockIdx.x * blockDim.x + threadIdx.x;  // E*64
    int e = idx >> 6, j = idx & 63;
    g_tenc[idx] = cosf(fmaf(rt[e], tw[j], tb[j]));
}

// ---------------- per-id counts --------------------------------------------
__global__ void k_count(const void* idsv) {
    int e = blockIdx.x * blockDim.x + threadIdx.x;
    if (e < E_NUM) atomicAdd(&g_cnt[load_id(idsv, e)], 1);
}

// ---------------- sorted-unique scan (warp shfl) ----------------------------
__global__ void k_scan(float* out, int write_ids) {
    __shared__ int wsum[32];
    int tid = threadIdx.x, lane = tid & 31, wid = tid >> 5;
    int base = tid * 32;
    int loc = 0;
#pragma unroll
    for (int i = 0; i < 32; i++) loc += (g_cnt[base + i] > 0) ? 1 : 0;
    int v = loc;
#pragma unroll
    for (int off = 1; off < 32; off <<= 1) {
        int t = __shfl_up_sync(0xFFFFFFFFu, v, off);
        if (lane >= off) v += t;
    }
    if (lane == 31) wsum[wid] = v;
    __syncthreads();
    if (wid == 0) {
        int w = wsum[lane];
#pragma unroll
        for (int off = 1; off < 32; off <<= 1) {
            int t = __shfl_up_sync(0xFFFFFFFFu, w, off);
            if (lane >= off) w += t;
        }
        wsum[lane] = w;
    }
    __syncthreads();
    int r = v - loc + (wid ? wsum[wid - 1] : 0);   // exclusive prefix
    for (int i = 0; i < 32; i++) {
        int id = base + i;
        if (g_cnt[id] > 0) {
            g_uid[r] = id;
            if (write_ids) out[r] = (float)id;
            r++;
        }
    }
}

// ---------------- scatter msg into per-id sums ------------------------------
__global__ void k_scatter(const void* idsv) {
    int idx = blockIdx.x * blockDim.x + threadIdx.x;  // E*64
    int e = idx >> 6;
    int c4 = (idx & 63) << 2;
    int id = load_id(idsv, e);
    float4 m = *reinterpret_cast<const float4*>(g_msg + (size_t)e * MSGD + c4);
    float* d = g_sums + (size_t)id * MSGD + c4;
    atomicAdd(d + 0, m.x);
    atomicAdd(d + 1, m.y);
    atomicAdd(d + 2, m.z);
    atomicAdd(d + 3, m.w);
}

// ---------------- agg = sums/count in unique-slot order ---------------------
__global__ void k_agg() {
    int idx = blockIdx.x * blockDim.x + threadIdx.x;  // NN*64
    int u = idx >> 6;
    int c4 = (idx & 63) << 2;
    int id = g_uid[u];
    float4 o = make_float4(0.f, 0.f, 0.f, 0.f);
    if (id < NN) {
        float cnt = (float)g_cnt[id];
        float4 s = *reinterpret_cast<const float4*>(g_sums + (size_t)id * MSGD + c4);
        o.x = s.x / cnt; o.y = s.y / cnt; o.z = s.z / cnt; o.w = s.w / cnt;
    }
    *reinterpret_cast<float4*>(g_agg + (size_t)u * MSGD + c4) = o;
}

// ---------------- tf32 mma.sync GEMM: C = A(MxK) * B(NxK)^T + bias ----------
// CTA tile 128x128, 8 warps (2x4), warp tile 64x32 of m16n8k8 frags.
// K chunks of 32 floats, double-buffered cp.async. Smem rows padded to 36.
#define KCH   32
#define APAD  36
#define STG_FLOATS (128 * APAD)            // per A or B tile per stage (4608)
#define STAGE_BYTES (2 * STG_FLOATS * 4)   // 36864
#define SMEM_BYTES  (2 * STAGE_BYTES)      // 73728

template <int CONCAT>
__device__ __forceinline__ void load_chunk(
    uint32_t smem_stage, int tid, int rowBase, int colBase, int k0,
    const float* __restrict__ A, const float* __restrict__ Bw, int K,
    const float* __restrict__ s0, const float* __restrict__ s1,
    const float* __restrict__ s2, const float* __restrict__ s3)
{
    const float* as;
    int ast;
    if (CONCAT) {
        if (k0 < 256)      { as = s0 + (size_t)rowBase * 256 + k0;         ast = 256; }
        else if (k0 < 512) { as = s1 + (size_t)rowBase * 256 + (k0 - 256); ast = 256; }
        else if (k0 < 640) { as = s2 + (size_t)rowBase * 128 + (k0 - 512); ast = 128; }
        else               { as = s3 + (size_t)rowBase * 64  + (k0 - 640); ast = 64;  }
    } else {
        as = A + (size_t)rowBase * K + k0;
        ast = K;
    }
#pragma unroll
    for (int i = 0; i < 4; ++i) {
        int idx = tid + (i << 8);
        int row = idx >> 3, seg = idx & 7;
        cp16(smem_stage + (uint32_t)(row * APAD + seg * 4) * 4,
             as + (size_t)row * ast + seg * 4);
    }
    const float* bs = Bw + (size_t)colBase * K + k0;
    uint32_t bbase = smem_stage + STG_FLOATS * 4;
#pragma unroll
    for (int i = 0; i < 4; ++i) {
        int idx = tid + (i << 8);
        int row = idx >> 3, seg = idx & 7;
        cp16(bbase + (uint32_t)(row * APAD + seg * 4) * 4,
             bs + (size_t)row * K + seg * 4);
    }
    asm volatile("cp.async.commit_group;" ::: "memory");
}

template <int CONCAT>
__global__ void __launch_bounds__(256, 2)
mma_gemm(const float* __restrict__ A, const float* __restrict__ Bw,
         const float* __restrict__ bias, float* __restrict__ Co,
         int K, int Nld, int relu,
         const float* __restrict__ s0, const float* __restrict__ s1,
         const float* __restrict__ s2, const float* __restrict__ s3)
{
    extern __shared__ char sm[];
    const int tid  = threadIdx.x;
    const int lane = tid & 31;
    const int wid  = tid >> 5;
    const int wm   = wid >> 2;      // 0..1  (64-row slabs)
    const int wn   = wid & 3;       // 0..3  (32-col slabs)
    const int rowBase = blockIdx.y * 128;
    const int colBase = blockIdx.x * 128;
    const uint32_t sb = smem_u32(sm);

    float acc[4][4][4];
#pragma unroll
    for (int mt = 0; mt < 4; mt++)
#pragma unroll
        for (int nt = 0; nt < 4; nt++)
#pragma unroll
            for (int r = 0; r < 4; r++) acc[mt][nt][r] = 0.0f;

    const int Cn = K / KCH;
    load_chunk<CONCAT>(sb, tid, rowBase, colBase, 0, A, Bw, K, s0, s1, s2, s3);

    for (int c = 0; c < Cn; ++c) {
        if (c + 1 < Cn) {
            load_chunk<CONCAT>(sb + ((c + 1) & 1) * STAGE_BYTES, tid, rowBase,
                               colBase, (c + 1) * KCH, A, Bw, K, s0, s1, s2, s3);
            cp_wait<1>();
        } else {
            cp_wait<0>();
        }
        __syncthreads();

        const float* As = (const float*)(sm + (size_t)(c & 1) * STAGE_BYTES);
        const float* Bs = As + STG_FLOATS;

#pragma unroll
        for (int ks = 0; ks < 4; ++ks) {
            const int kk = ks * 8 + (lane & 3);
            uint32_t a[4][4];
#pragma unroll
            for (int mt = 0; mt < 4; mt++) {
                int r0 = wm * 64 + mt * 16 + (lane >> 2);
                a[mt][0] = lds_tf(As + r0 * APAD + kk);
                a[mt][1] = lds_tf(As + (r0 + 8) * APAD + kk);
                a[mt][2] = lds_tf(As + r0 * APAD + kk + 4);
                a[mt][3] = lds_tf(As + (r0 + 8) * APAD + kk + 4);
            }
            uint32_t b[4][2];
#pragma unroll
            for (int nt = 0; nt < 4; nt++) {
                int n0 = wn * 32 + nt * 8 + (lane >> 2);
                b[nt][0] = lds_tf(Bs + n0 * APAD + kk);
                b[nt][1] = lds_tf(Bs + n0 * APAD + kk + 4);
            }
#pragma unroll
            for (int mt = 0; mt < 4; mt++)
#pragma unroll
                for (int nt = 0; nt < 4; nt++)
                    mma8(acc[mt][nt], a[mt], b[nt]);
        }
        __syncthreads();
    }

    // ---- epilogue: bias (+relu), float2 stores
#pragma unroll
    for (int mt = 0; mt < 4; mt++) {
        int r0 = rowBase + wm * 64 + mt * 16 + (lane >> 2);
#pragma unroll
        for (int nt = 0; nt < 4; nt++) {
            int c0 = colBase + wn * 32 + nt * 8 + (lane & 3) * 2;
            float bv0 = bias[c0], bv1 = bias[c0 + 1];
            float2 o0, o1;
            o0.x = acc[mt][nt][0] + bv0;
            o0.y = acc[mt][nt][1] + bv1;
            o1.x = acc[mt][nt][2] + bv0;
            o1.y = acc[mt][nt][3] + bv1;
            if (relu) {
                o0.x = fmaxf(o0.x, 0.f); o0.y = fmaxf(o0.y, 0.f);
                o1.x = fmaxf(o1.x, 0.f); o1.y = fmaxf(o1.y, 0.f);
            }
            *reinterpret_cast<float2*>(Co + (size_t)r0 * Nld + c0) = o0;
            *reinterpret_cast<float2*>(Co + (size_t)(r0 + 8) * Nld + c0) = o1;
        }
    }
}

// ---------------- GRU gates + output ----------------------------------------
__global__ void k_gate(const float* __restrict__ dstm, float* __restrict__ out,
                       int mem_off) {
    int idx = blockIdx.x * blockDim.x + threadIdx.x;  // NN*DM
    int u = idx >> 8;
    int c = idx & 255;
    const float* gi = g_gih + (size_t)u * (3 * DM);
    const float* gh = g_ghh + (size_t)u * (3 * DM);
    float r = 1.0f / (1.0f + expf(-(gi[c] + gh[c])));
    float z = 1.0f / (1.0f + expf(-(gi[256 + c] + gh[256 + c])));
    float n = tanhf(gi[512 + c] + r * gh[512 + c]);
    float prev = dstm[idx];
    out[mem_off + idx] = (1.0f - z) * n + z * prev;
}

// ---------------- launch -----------------------------------------------------
extern "C" void kernel_launch(void* const* d_in, const int* in_sizes, int n_in,
                              void* d_out, int out_size)
{
    const float* rel_time = (const float*)d_in[0];
    const float* srcm     = (const float*)d_in[1];
    const float* dstm     = (const float*)d_in[2];
    const float* edgef    = (const float*)d_in[3];
    const void*  idsv     =               d_in[4];
    const float* tw       = (const float*)d_in[5];
    const float* tb       = (const float*)d_in[6];
    const float* w1       = (const float*)d_in[7];
    const float* b1       = (const float*)d_in[8];
    const float* w2       = (const float*)d_in[9];
    const float* b2       = (const float*)d_in[10];
    const float* wih      = (const float*)d_in[11];
    const float* whh      = (const float*)d_in[12];
    const float* bih      = (const float*)d_in[13];
    const float* bhh      = (const float*)d_in[14];
    float* out = (float*)d_out;

    int write_ids = (out_size >= NN + NN * DM) ? 1 : 0;
    int mem_off   = write_ids ? NN : 0;

    float *p_h, *p_msg, *p_agg, *p_gih, *p_ghh, *p_tenc;
    cudaGetSymbolAddress((void**)&p_h,    g_h);
    cudaGetSymbolAddress((void**)&p_msg,  g_msg);
    cudaGetSymbolAddress((void**)&p_agg,  g_agg);
    cudaGetSymbolAddress((void**)&p_gih,  g_gih);
    cudaGetSymbolAddress((void**)&p_ghh,  g_ghh);
    cudaGetSymbolAddress((void**)&p_tenc, g_tenc);

    cudaFuncSetAttribute(mma_gemm<0>, cudaFuncAttributeMaxDynamicSharedMemorySize, SMEM_BYTES);
    cudaFuncSetAttribute(mma_gemm<1>, cudaFuncAttributeMaxDynamicSharedMemorySize, SMEM_BYTES);

    k_detect<<<1, 32>>>((const int*)idsv);
    k_zero<<<(NN * MSGD) / 256, 256>>>(out, write_ids);
    k_count<<<E_NUM / 256, 256>>>(idsv);
    k_scan<<<1, 1024>>>(out, write_ids);
    k_tenc<<<(E_NUM * 64) / 256, 256>>>(rel_time, tw, tb);

    // GEMM1: h = relu([src|dst|edge|t_enc] @ w1^T + b1)   131072 x 512, K=704
    mma_gemm<1><<<dim3(HIDN / 128, E_NUM / 128), 256, SMEM_BYTES>>>(
        nullptr, w1, b1, p_h, 704, HIDN, 1, srcm, dstm, edgef, p_tenc);

    // GEMM2: msg = h @ w2^T + b2                          131072 x 256, K=512
    mma_gemm<0><<<dim3(MSGD / 128, E_NUM / 128), 256, SMEM_BYTES>>>(
        p_h, w2, b2, p_msg, 512, MSGD, 0, nullptr, nullptr, nullptr, nullptr);

    k_scatter<<<(E_NUM * 64) / 256, 256>>>(idsv);
    k_agg<<<(NN * 64) / 256, 256>>>();

    // GRU: gi = agg @ wih^T + bih ; gh = prev @ whh^T + bhh   32768 x 768, K=256
    mma_gemm<0><<<dim3((3 * DM) / 128, NN / 128), 256, SMEM_BYTES>>>(
        p_agg, wih, bih, p_gih, 256, 3 * DM, 0, nullptr, nullptr, nullptr, nullptr);
    mma_gemm<0><<<dim3((3 * DM) / 128, NN / 128), 256, SMEM_BYTES>>>(
        dstm, whh, bhh, p_ghh, 256, 3 * DM, 0, nullptr, nullptr, nullptr, nullptr);

    k_gate<<<(NN * DM) / 256, 256>>>(dstm, out, mem_off);
}